// round 16
// baseline (speedup 1.0000x reference)
#include <cuda_runtime.h>

// Model_76811195122407: 3-layer LIF SNN -- perf round (numerics frozen = R15)
// L1 (K=128): strided-4 slices, combine A=(c0+c1)+(c2+c3)
// L2/L3 (K=100): VF4-IC2 main (12 chunk-pairs), u=v0+v1, combine A,
//                scalar fma tail k=96..99
// LIF: m = fsub(fma(0.9,m,c), r)
// Perf: hoisted activation loads (one LDS per chunk per neuron-block) +
//       packed fma.rn.f32x2 / add.rn.f32x2 (bitwise == two scalar RN ops).

#define Tn   50
#define Bn   16384
#define DIN  128
#define Hn   100
#define HPAD 104
#define DOUT 128
#define BETA 0.9f
#define THR  0.5f

#define BB   32
#define NPT  13
#define NPTO 16

#define KC_IN (DIN / 4)   // 32
#define KC_H  (HPAD / 4)  // 26 (chunks 0..24 used; 25 is pad, never read)

#define W1_F (HPAD * DIN)
#define W2_F (HPAD * HPAD)
#define W3_F (DOUT * HPAD)
#define XS_F (DIN * BB)
#define S1_F (HPAD * BB)
#define S2_F (HPAD * BB)
#define SMEM_FLOATS (W1_F + W2_F + W3_F + XS_F + S1_F + S2_F)

typedef unsigned long long u64;

extern __shared__ float smem[];

__device__ __forceinline__ u64 fma2(u64 a, u64 b, u64 c)
{
    u64 d;
    asm("fma.rn.f32x2 %0, %1, %2, %3;" : "=l"(d) : "l"(a), "l"(b), "l"(c));
    return d;
}
__device__ __forceinline__ u64 add2(u64 a, u64 b)
{
    u64 d;
    asm("add.rn.f32x2 %0, %1, %2;" : "=l"(d) : "l"(a), "l"(b));
    return d;
}
__device__ __forceinline__ void unpk(u64 v, float& lo, float& hi)
{
    asm("mov.b64 {%0, %1}, %2;" : "=f"(lo), "=f"(hi) : "l"(v));
}

__device__ __forceinline__ void lif_update(float& m, float c, float& spk)
{
    float r = (m > THR) ? THR : 0.f;
    float t = __fmaf_rn(BETA, m, c);
    m = __fsub_rn(t, r);
    spk = (m > THR) ? 1.f : 0.f;
}

// ---- L1: NB neurons, K=128, strided-4 packed, combine A ----
template<int NB>
__device__ __forceinline__ void dot128_block(const ulonglong2* __restrict__ w2,
                                             const ulonglong2* __restrict__ a2,
                                             int l, float* __restrict__ cout)
{
    u64 c01[NB], c23[NB];
#pragma unroll
    for (int i = 0; i < NB; i++) { c01[i] = 0ull; c23[i] = 0ull; }
#pragma unroll 4
    for (int kc = 0; kc < KC_IN; kc++) {
        ulonglong2 av = a2[kc * BB + l];
#pragma unroll
        for (int i = 0; i < NB; i++) {
            ulonglong2 w = w2[i * KC_IN + kc];
            c01[i] = fma2(w.x, av.x, c01[i]);
            c23[i] = fma2(w.y, av.y, c23[i]);
        }
    }
#pragma unroll
    for (int i = 0; i < NB; i++) {
        float c0, c1, c2, c3;
        unpk(c01[i], c0, c1);
        unpk(c23[i], c2, c3);
        cout[i] = __fadd_rn(__fadd_rn(c0, c1), __fadd_rn(c2, c3));
    }
}

// ---- L2/L3: NB neurons, K=100, IC2 main + scalar tail ----
template<int NB>
__device__ __forceinline__ void dot100_block(const ulonglong2* __restrict__ w2,
                                             const float4* __restrict__ w4,
                                             const ulonglong2* __restrict__ a2,
                                             const float4* __restrict__ a4,
                                             int l, float* __restrict__ cout)
{
    u64 v0a[NB], v0b[NB], v1a[NB], v1b[NB];
#pragma unroll
    for (int i = 0; i < NB; i++) { v0a[i]=0ull; v0b[i]=0ull; v1a[i]=0ull; v1b[i]=0ull; }
#pragma unroll 3
    for (int p = 0; p < 12; p++) {
        ulonglong2 a0 = a2[(2*p)   * BB + l];
        ulonglong2 a1 = a2[(2*p+1) * BB + l];
#pragma unroll
        for (int i = 0; i < NB; i++) {
            ulonglong2 w0 = w2[i * KC_H + 2*p];
            ulonglong2 w1 = w2[i * KC_H + 2*p + 1];
            v0a[i] = fma2(w0.x, a0.x, v0a[i]);
            v0b[i] = fma2(w0.y, a0.y, v0b[i]);
            v1a[i] = fma2(w1.x, a1.x, v1a[i]);
            v1b[i] = fma2(w1.y, a1.y, v1b[i]);
        }
    }
    float4 at = a4[24 * BB + l];   // tail activations, loaded once
#pragma unroll
    for (int i = 0; i < NB; i++) {
        u64 ua = add2(v0a[i], v1a[i]);
        u64 ub = add2(v0b[i], v1b[i]);
        float u0, u1, u2, u3;
        unpk(ua, u0, u1);
        unpk(ub, u2, u3);
        float h = __fadd_rn(__fadd_rn(u0, u1), __fadd_rn(u2, u3));
        float4 wt = w4[i * KC_H + 24];
        h = __fmaf_rn(wt.x, at.x, h);
        h = __fmaf_rn(wt.y, at.y, h);
        h = __fmaf_rn(wt.z, at.z, h);
        h = __fmaf_rn(wt.w, at.w, h);
        cout[i] = h;
    }
}

__global__ void __launch_bounds__(256, 1) snn_lif3_kernel(
    const float* __restrict__ x,
    const float* __restrict__ W1,
    const float* __restrict__ W2,
    const float* __restrict__ W3,
    float* __restrict__ out)
{
    float* w1s = smem;
    float* w2s = w1s + W1_F;
    float* w3s = w2s + W2_F;
    float* xs  = w3s + W3_F;
    float* s1  = xs + XS_F;
    float* s2  = s1 + S1_F;

    const int tid = threadIdx.x;
    const int l   = tid & 31;
    const int g   = tid >> 5;

    for (int i = tid; i < W1_F + W2_F + W3_F; i += 256) w1s[i] = 0.f;
    __syncthreads();
    for (int i = tid; i < Hn * DIN; i += 256) w1s[i] = W1[i];
    for (int i = tid; i < Hn * Hn; i += 256) {
        int n = i / Hn, k = i - n * Hn;
        w2s[n * HPAD + k] = W2[i];
    }
    for (int i = tid; i < DOUT * Hn; i += 256) {
        int n = i / Hn, k = i - n * Hn;
        w3s[n * HPAD + k] = W3[i];
    }
    __syncthreads();

    const ulonglong2* xs2  = (const ulonglong2*)xs;
    const ulonglong2* s1_2 = (const ulonglong2*)s1;
    const ulonglong2* s2_2 = (const ulonglong2*)s2;
    const float4*     s1_4 = (const float4*)s1;
    const float4*     s2_4 = (const float4*)s2;
    const ulonglong2* w1_2 = (const ulonglong2*)w1s;
    const ulonglong2* w2_2 = (const ulonglong2*)w2s;
    const ulonglong2* w3_2 = (const ulonglong2*)w3s;
    const float4*     w2_4 = (const float4*)w2s;
    const float4*     w3_4 = (const float4*)w3s;

    const int n0  = g * NPT;
    const int n0o = g * NPTO;
    const int b   = blockIdx.x * BB + l;

    float m1[NPT], m2[NPT], m3[NPTO];
#pragma unroll
    for (int i = 0; i < NPT; i++)  { m1[i] = 0.f; m2[i] = 0.f; }
#pragma unroll
    for (int i = 0; i < NPTO; i++) { m3[i] = 0.f; }

    const size_t MEMOFF = (size_t)Tn * Bn * DOUT;

    for (int t = 0; t < Tn; t++) {
        const float4* gx =
            (const float4*)(x + ((size_t)t * Bn + (size_t)blockIdx.x * BB) * DIN);
#pragma unroll
        for (int j = 0; j < 4; j++) {
            int idx = tid + j * 256;
            float4 v = gx[idx];
            int row = idx >> 5;
            int kc  = idx & 31;
            ((float4*)xs)[kc * BB + row] = v;
        }
        __syncthreads();

        // ===== layer 1: K=128 =====
        {
            float c[NPT];
            dot128_block<NPT>(&w1_2[n0 * KC_IN], xs2, l, c);
#pragma unroll
            for (int i = 0; i < NPT; i++) {
                float s;
                lif_update(m1[i], c[i], s);
                int n = n0 + i;
                s1[(n >> 2) * (BB * 4) + l * 4 + (n & 3)] = s;
            }
        }
        __syncthreads();

        // ===== layer 2: K=100 (7 + 6 neuron sub-blocks) =====
        {
            float c[NPT];
            dot100_block<7>(&w2_2[n0 * KC_H], &w2_4[n0 * KC_H], s1_2, s1_4, l, &c[0]);
            dot100_block<6>(&w2_2[(n0 + 7) * KC_H], &w2_4[(n0 + 7) * KC_H], s1_2, s1_4, l, &c[7]);
#pragma unroll
            for (int i = 0; i < NPT; i++) {
                float s;
                lif_update(m2[i], c[i], s);
                int n = n0 + i;
                s2[(n >> 2) * (BB * 4) + l * 4 + (n & 3)] = s;
            }
        }
        __syncthreads();

        // ===== layer 3: K=100 (8 + 8 neuron sub-blocks) =====
        {
            float c[NPTO];
            dot100_block<8>(&w3_2[n0o * KC_H], &w3_4[n0o * KC_H], s2_2, s2_4, l, &c[0]);
            dot100_block<8>(&w3_2[(n0o + 8) * KC_H], &w3_4[(n0o + 8) * KC_H], s2_2, s2_4, l, &c[8]);

            size_t obase = ((size_t)t * Bn + b) * DOUT + n0o;
#pragma unroll
            for (int i = 0; i < NPTO; i += 4) {
                float4 sv4, mv4;
                lif_update(m3[i],   c[i],   sv4.x); mv4.x = m3[i];
                lif_update(m3[i+1], c[i+1], sv4.y); mv4.y = m3[i+1];
                lif_update(m3[i+2], c[i+2], sv4.z); mv4.z = m3[i+2];
                lif_update(m3[i+3], c[i+3], sv4.w); mv4.w = m3[i+3];
                *(float4*)(out + obase + i)          = sv4;
                *(float4*)(out + MEMOFF + obase + i) = mv4;
            }
        }
        __syncthreads();
    }
}

extern "C" void kernel_launch(void* const* d_in, const int* in_sizes, int n_in,
                              void* d_out, int out_size)
{
    const float* x  = (const float*)d_in[0];
    const float* W1 = (const float*)d_in[1];
    const float* W2 = (const float*)d_in[2];
    const float* W3 = (const float*)d_in[3];
    float* out = (float*)d_out;

    size_t smem_bytes = (size_t)SMEM_FLOATS * sizeof(float);
    cudaFuncSetAttribute(snn_lif3_kernel,
                         cudaFuncAttributeMaxDynamicSharedMemorySize,
                         (int)smem_bytes);

    dim3 grid(Bn / BB);
    dim3 block(256);
    snn_lif3_kernel<<<grid, block, smem_bytes>>>(x, W1, W2, W3, out);
}